// round 1
// baseline (speedup 1.0000x reference)
#include <cuda_runtime.h>
#include <math.h>

#define S_LEN    2048
#define D_MODEL  1024
#define N_HEADS  16
#define HEAD_DIM 64
#define BATCH    2
#define NTOK     (BATCH * S_LEN)   // 4096

// -------- scratch (device globals: no allocations allowed) --------
__device__ float g_Q[NTOK * D_MODEL];
__device__ float g_K[NTOK * D_MODEL];
__device__ float g_V[NTOK * D_MODEL];
__device__ float g_C[NTOK * D_MODEL];
__device__ float g_cos[S_LEN * 32];
__device__ float g_sin[S_LEN * 32];

// =================================================================
// SGEMM: C[M,N] = A[M,K] @ B[N,K]^T   (both operands K-major)
// 64x64 tile, BK=16, 256 threads, 4x4 micro-tile
// =================================================================
#define BM 64
#define BN 64
#define BK 16
#define PAD 68   // row stride in smem (multiple of 4 for float4)

__global__ __launch_bounds__(256) void sgemm_tn(
    const float* __restrict__ A, const float* __restrict__ B,
    float* __restrict__ C, int M, int N, int K)
{
    __shared__ __align__(16) float Ast[BK][PAD];
    __shared__ __align__(16) float Bst[BK][PAD];

    const int t  = threadIdx.x;
    const int tx = t & 15;
    const int ty = t >> 4;
    const int mb = blockIdx.y * BM;
    const int nb = blockIdx.x * BN;

    const int lr = t >> 2;         // 0..63 : row within tile
    const int lk = (t & 3) * 4;    // 0,4,8,12 : k offset

    float acc[4][4];
#pragma unroll
    for (int i = 0; i < 4; i++)
#pragma unroll
        for (int j = 0; j < 4; j++) acc[i][j] = 0.f;

    const float* Arow = A + (size_t)(mb + lr) * K + lk;
    const float* Brow = B + (size_t)(nb + lr) * K + lk;

    for (int kt = 0; kt < K; kt += BK) {
        float4 a4 = *(const float4*)(Arow + kt);
        float4 b4 = *(const float4*)(Brow + kt);
        Ast[lk + 0][lr] = a4.x; Ast[lk + 1][lr] = a4.y;
        Ast[lk + 2][lr] = a4.z; Ast[lk + 3][lr] = a4.w;
        Bst[lk + 0][lr] = b4.x; Bst[lk + 1][lr] = b4.y;
        Bst[lk + 2][lr] = b4.z; Bst[lk + 3][lr] = b4.w;
        __syncthreads();

#pragma unroll
        for (int k = 0; k < BK; k++) {
            float4 av = *(const float4*)&Ast[k][ty * 4];
            float4 bv = *(const float4*)&Bst[k][tx * 4];
            float ar[4] = {av.x, av.y, av.z, av.w};
            float br[4] = {bv.x, bv.y, bv.z, bv.w};
#pragma unroll
            for (int i = 0; i < 4; i++)
#pragma unroll
                for (int j = 0; j < 4; j++)
                    acc[i][j] = fmaf(ar[i], br[j], acc[i][j]);
        }
        __syncthreads();
    }

#pragma unroll
    for (int i = 0; i < 4; i++) {
        float4 o = make_float4(acc[i][0], acc[i][1], acc[i][2], acc[i][3]);
        *(float4*)&C[(size_t)(mb + ty * 4 + i) * N + nb + tx * 4] = o;
    }
}

// =================================================================
// RoPE cos/sin table: pos in [0,2048), freq index f in [0,32)
// Reproduce jnp fp32 angle exactly, then exact sin/cos (fp64) to
// dodge --use_fast_math __sinf range-reduction error at ang~2000.
// =================================================================
__global__ void rope_table_kernel()
{
    int i = blockIdx.x * blockDim.x + threadIdx.x;
    if (i >= S_LEN * 32) return;
    int pos = i >> 5;
    int f   = i & 31;
    float e     = (float)(2 * f) / 64.0f;
    float pw    = powf(10000.0f, e);
    float invf  = 1.0f / pw;
    float angf  = (float)pos * invf;    // fp32 angle, matches reference
    double s, c;
    sincos((double)angf, &s, &c);
    g_cos[i] = (float)c;
    g_sin[i] = (float)s;
}

// =================================================================
// RoPE apply (interleaved pairs within each 64-dim head) + optional scale
// X: [NTOK, D_MODEL]
// =================================================================
__global__ void rope_apply_kernel(float* __restrict__ X, float scale)
{
    int idx = blockIdx.x * blockDim.x + threadIdx.x;   // 0 .. NTOK*512
    if (idx >= NTOK * (D_MODEL / 2)) return;
    int tok = idx >> 9;            // / 512
    int p   = idx & 511;
    int head = p >> 5;             // / 32
    int fi   = p & 31;
    int pos  = tok & (S_LEN - 1);  // tok % 2048

    float c = g_cos[pos * 32 + fi];
    float s = g_sin[pos * 32 + fi];

    float2* ptr = (float2*)(X + (size_t)tok * D_MODEL + head * HEAD_DIM + fi * 2);
    float2 v = *ptr;
    float r1 = v.x * c - v.y * s;
    float r2 = v.x * s + v.y * c;
    v.x = r1 * scale;
    v.y = r2 * scale;
    *ptr = v;
}

// =================================================================
// Flash attention, causal. One CTA per (q-tile of 64 rows, head, batch).
// Q pre-scaled by 1/sqrt(hd). 256 threads = 16x16, 4x4 micro-tile.
// smem: Qt[64][68] (transposed j-major), Kt[64][68] (transposed),
//       Vs[64][68] (natural), Ps[64][68] (natural)
// =================================================================
#define ATT_SMEM (4 * 64 * PAD * (int)sizeof(float))

__global__ __launch_bounds__(256) void attn_kernel(
    const float* __restrict__ Q, const float* __restrict__ K,
    const float* __restrict__ V, float* __restrict__ Ctx)
{
    extern __shared__ __align__(16) float sm[];
    float* Qt = sm;                  // [j][r]
    float* Kt = Qt + 64 * PAD;       // [j][c]
    float* Vs = Kt + 64 * PAD;       // [j][c]  j = k-token-in-tile, c = hd
    float* Ps = Vs + 64 * PAD;       // [r][j]

    const int qb = blockIdx.x * 64;
    const int h  = blockIdx.y;
    const int b  = blockIdx.z;

    const int t  = threadIdx.x;
    const int tx = t & 15;
    const int ty = t >> 4;

    const int lr = t >> 4;           // 0..15? no: 256/16 = 16 -> need 64 rows
    // tile load mapping: each thread loads one float4: row = t/16 covers 16 rows
    // -> loop 4x to cover 64 rows
    const int ljr = t >> 4;          // base row group (0..15)
    const int lj  = (t & 15) * 4;    // col offset (0..60)

    const float* qbase = Q + ((size_t)b * S_LEN + qb) * D_MODEL + h * HEAD_DIM;

    // load Q tile transposed: Qt[j][r]
#pragma unroll
    for (int rr = 0; rr < 4; rr++) {
        int r = ljr + rr * 16;
        float4 q4 = *(const float4*)&qbase[(size_t)r * D_MODEL + lj];
        Qt[(lj + 0) * PAD + r] = q4.x;
        Qt[(lj + 1) * PAD + r] = q4.y;
        Qt[(lj + 2) * PAD + r] = q4.z;
        Qt[(lj + 3) * PAD + r] = q4.w;
    }

    float m_[4], l_[4], o_[4][4];
#pragma unroll
    for (int i = 0; i < 4; i++) {
        m_[i] = -1e30f;
        l_[i] = 0.f;
#pragma unroll
        for (int j = 0; j < 4; j++) o_[i][j] = 0.f;
    }

    for (int kt = 0; kt <= qb; kt += 64) {
        const float* kbase = K + ((size_t)b * S_LEN + kt) * D_MODEL + h * HEAD_DIM;
        const float* vbase = V + ((size_t)b * S_LEN + kt) * D_MODEL + h * HEAD_DIM;

        __syncthreads();   // previous iter's Ps/Vs reads done before overwrite
#pragma unroll
        for (int rr = 0; rr < 4; rr++) {
            int r = ljr + rr * 16;
            float4 k4 = *(const float4*)&kbase[(size_t)r * D_MODEL + lj];
            Kt[(lj + 0) * PAD + r] = k4.x;
            Kt[(lj + 1) * PAD + r] = k4.y;
            Kt[(lj + 2) * PAD + r] = k4.z;
            Kt[(lj + 3) * PAD + r] = k4.w;
            float4 v4 = *(const float4*)&vbase[(size_t)r * D_MODEL + lj];
            *(float4*)&Vs[r * PAD + lj] = v4;
        }
        __syncthreads();

        // S = Q K^T  (4x4 per thread)
        float s[4][4];
#pragma unroll
        for (int i = 0; i < 4; i++)
#pragma unroll
            for (int j = 0; j < 4; j++) s[i][j] = 0.f;

#pragma unroll 8
        for (int j = 0; j < 64; j++) {
            float4 av = *(const float4*)&Qt[j * PAD + ty * 4];
            float4 bv = *(const float4*)&Kt[j * PAD + tx * 4];
            float ar[4] = {av.x, av.y, av.z, av.w};
            float br[4] = {bv.x, bv.y, bv.z, bv.w};
#pragma unroll
            for (int i = 0; i < 4; i++)
#pragma unroll
                for (int jj = 0; jj < 4; jj++)
                    s[i][jj] = fmaf(ar[i], br[jj], s[i][jj]);
        }

        // causal mask: only the diagonal tile needs it
        if (kt == qb) {
#pragma unroll
            for (int i = 0; i < 4; i++)
#pragma unroll
                for (int jj = 0; jj < 4; jj++)
                    if (tx * 4 + jj > ty * 4 + i) s[i][jj] = -1e30f;
        }

        // online softmax update (row reduction over 16 lanes sharing rows)
#pragma unroll
        for (int i = 0; i < 4; i++) {
            float rm = fmaxf(fmaxf(s[i][0], s[i][1]), fmaxf(s[i][2], s[i][3]));
#pragma unroll
            for (int off = 1; off < 16; off <<= 1)
                rm = fmaxf(rm, __shfl_xor_sync(0xffffffffu, rm, off));
            float nm = fmaxf(m_[i], rm);
            float alpha = expf(m_[i] - nm);
            float rs = 0.f;
#pragma unroll
            for (int jj = 0; jj < 4; jj++) {
                float p = expf(s[i][jj] - nm);
                s[i][jj] = p;
                rs += p;
            }
#pragma unroll
            for (int off = 1; off < 16; off <<= 1)
                rs += __shfl_xor_sync(0xffffffffu, rs, off);
            l_[i] = l_[i] * alpha + rs;
            m_[i] = nm;
#pragma unroll
            for (int jj = 0; jj < 4; jj++) o_[i][jj] *= alpha;
        }

        // write P tile
#pragma unroll
        for (int i = 0; i < 4; i++)
            *(float4*)&Ps[(ty * 4 + i) * PAD + tx * 4] =
                make_float4(s[i][0], s[i][1], s[i][2], s[i][3]);
        __syncthreads();

        // O += P @ V
#pragma unroll 8
        for (int j = 0; j < 64; j++) {
            float4 vv = *(const float4*)&Vs[j * PAD + tx * 4];
#pragma unroll
            for (int i = 0; i < 4; i++) {
                float p = Ps[(ty * 4 + i) * PAD + j];
                o_[i][0] = fmaf(p, vv.x, o_[i][0]);
                o_[i][1] = fmaf(p, vv.y, o_[i][1]);
                o_[i][2] = fmaf(p, vv.z, o_[i][2]);
                o_[i][3] = fmaf(p, vv.w, o_[i][3]);
            }
        }
    }

    // epilogue: normalize & store to ctx in (b, s, h*hd) layout
    float* cbase = Ctx + ((size_t)b * S_LEN + qb) * D_MODEL + h * HEAD_DIM;
#pragma unroll
    for (int i = 0; i < 4; i++) {
        float inv = 1.0f / l_[i];
        float4 o = make_float4(o_[i][0] * inv, o_[i][1] * inv,
                               o_[i][2] * inv, o_[i][3] * inv);
        *(float4*)&cbase[(size_t)(ty * 4 + i) * D_MODEL + tx * 4] = o;
    }
}

// =================================================================
// Launch
// =================================================================
extern "C" void kernel_launch(void* const* d_in, const int* in_sizes, int n_in,
                              void* d_out, int out_size)
{
    const float* x  = (const float*)d_in[0];
    const float* Wq = (const float*)d_in[1];
    const float* Wk = (const float*)d_in[2];
    const float* Wv = (const float*)d_in[3];
    const float* Wo = (const float*)d_in[4];
    float* out = (float*)d_out;

    float *Q, *K, *V, *C;
    cudaGetSymbolAddress((void**)&Q, g_Q);
    cudaGetSymbolAddress((void**)&K, g_K);
    cudaGetSymbolAddress((void**)&V, g_V);
    cudaGetSymbolAddress((void**)&C, g_C);

    dim3 gemm_grid(D_MODEL / BN, NTOK / BM);   // (16, 64)

    // QKV projections
    sgemm_tn<<<gemm_grid, 256>>>(x, Wq, Q, NTOK, D_MODEL, D_MODEL);
    sgemm_tn<<<gemm_grid, 256>>>(x, Wk, K, NTOK, D_MODEL, D_MODEL);
    sgemm_tn<<<gemm_grid, 256>>>(x, Wv, V, NTOK, D_MODEL, D_MODEL);

    // RoPE
    rope_table_kernel<<<(S_LEN * 32 + 255) / 256, 256>>>();
    int rope_threads = NTOK * (D_MODEL / 2);
    rope_apply_kernel<<<(rope_threads + 255) / 256, 256>>>(Q, 0.125f); // fold 1/sqrt(64)
    rope_apply_kernel<<<(rope_threads + 255) / 256, 256>>>(K, 1.0f);

    // attention
    static int smem_set = 0;
    cudaFuncSetAttribute(attn_kernel, cudaFuncAttributeMaxDynamicSharedMemorySize, ATT_SMEM);
    (void)smem_set;
    attn_kernel<<<dim3(S_LEN / 64, N_HEADS, BATCH), 256, ATT_SMEM>>>(Q, K, V, C);

    // output projection
    sgemm_tn<<<gemm_grid, 256>>>(C, Wo, out, NTOK, D_MODEL, D_MODEL);
}

// round 2
// speedup vs baseline: 1.6125x; 1.6125x over previous
#include <cuda_runtime.h>
#include <math.h>

#define S_LEN    2048
#define D_MODEL  1024
#define N_HEADS  16
#define HEAD_DIM 64
#define BATCH    2
#define NTOK     (BATCH * S_LEN)   // 4096

// -------- scratch (device globals: no allocations allowed) --------
__device__ float g_Q[NTOK * D_MODEL];
__device__ float g_K[NTOK * D_MODEL];
__device__ float g_V[NTOK * D_MODEL];
__device__ float g_C[NTOK * D_MODEL];
__device__ float g_cos[S_LEN * 32];
__device__ float g_sin[S_LEN * 32];

// =================================================================
// TF32 tensor-core GEMM: C[M,N] = A[M,K] @ B[N,K]^T
// 128x128x16 block tile, 256 threads (8 warps, 2x4), 64x32 warp tile,
// mma.sync.m16n8k8.tf32, cp.async double-buffered smem.
// =================================================================
#define AST 20   // smem row stride for 16 k-floats (+4 pad: conflict-free frags, float4 aligned)

__device__ __forceinline__ unsigned f2tf(float x) {
    unsigned u;
    asm("cvt.rna.tf32.f32 %0, %1;" : "=r"(u) : "f"(x));
    return u;
}

__global__ __launch_bounds__(256, 2) void gemm_tf32(
    const float* __restrict__ A, const float* __restrict__ B,
    float* __restrict__ C, int M, int N, int K)
{
    __shared__ __align__(16) float As[2][128 * AST];
    __shared__ __align__(16) float Bs[2][128 * AST];

    const int t    = threadIdx.x;
    const int warp = t >> 5, lane = t & 31;
    const int g    = lane >> 2, tig = lane & 3;
    const int wm   = (warp >> 2) * 64;   // warp row offset
    const int wn   = (warp & 3) * 32;    // warp col offset
    const int mb   = blockIdx.y * 128;
    const int nb   = blockIdx.x * 128;

    float acc[4][4][4];
#pragma unroll
    for (int mt = 0; mt < 4; mt++)
#pragma unroll
        for (int nt = 0; nt < 4; nt++)
#pragma unroll
            for (int i = 0; i < 4; i++) acc[mt][nt][i] = 0.f;

    // stage loader: 128x16 tile of A and B each = 512 float4 each; 256 threads x 2
#define LOAD_STAGE(buf, kt)                                                        \
    do {                                                                           \
        _Pragma("unroll")                                                          \
        for (int i = 0; i < 2; i++) {                                              \
            int idx = t + i * 256;                                                 \
            int row = idx >> 2, col = (idx & 3) * 4;                               \
            unsigned da = (unsigned)__cvta_generic_to_shared(                      \
                &As[buf][row * AST + col]);                                        \
            const float* ga = A + (size_t)(mb + row) * K + (kt) + col;             \
            asm volatile("cp.async.cg.shared.global [%0], [%1], 16;"               \
                         :: "r"(da), "l"(ga));                                     \
            unsigned db = (unsigned)__cvta_generic_to_shared(                      \
                &Bs[buf][row * AST + col]);                                        \
            const float* gb = B + (size_t)(nb + row) * K + (kt) + col;             \
            asm volatile("cp.async.cg.shared.global [%0], [%1], 16;"               \
                         :: "r"(db), "l"(gb));                                     \
        }                                                                          \
        asm volatile("cp.async.commit_group;");                                    \
    } while (0)

    int buf = 0;
    LOAD_STAGE(0, 0);

    for (int kt = 0; kt < K; kt += 16) {
        asm volatile("cp.async.wait_group 0;");
        __syncthreads();
        if (kt + 16 < K) LOAD_STAGE(buf ^ 1, kt + 16);

        const float* Ab = As[buf];
        const float* Bb = Bs[buf];

#pragma unroll
        for (int ks = 0; ks < 2; ks++) {
            const int kb = ks * 8;
            unsigned af[4][4], bf[4][2];
#pragma unroll
            for (int mt = 0; mt < 4; mt++) {
                int r0 = wm + mt * 16 + g;
                af[mt][0] = f2tf(Ab[r0 * AST + kb + tig]);
                af[mt][1] = f2tf(Ab[(r0 + 8) * AST + kb + tig]);
                af[mt][2] = f2tf(Ab[r0 * AST + kb + tig + 4]);
                af[mt][3] = f2tf(Ab[(r0 + 8) * AST + kb + tig + 4]);
            }
#pragma unroll
            for (int nt = 0; nt < 4; nt++) {
                int n0 = wn + nt * 8 + g;
                bf[nt][0] = f2tf(Bb[n0 * AST + kb + tig]);
                bf[nt][1] = f2tf(Bb[n0 * AST + kb + tig + 4]);
            }
#pragma unroll
            for (int mt = 0; mt < 4; mt++)
#pragma unroll
                for (int nt = 0; nt < 4; nt++)
                    asm volatile(
                        "mma.sync.aligned.m16n8k8.row.col.f32.tf32.tf32.f32 "
                        "{%0,%1,%2,%3},{%4,%5,%6,%7},{%8,%9},{%0,%1,%2,%3};"
                        : "+f"(acc[mt][nt][0]), "+f"(acc[mt][nt][1]),
                          "+f"(acc[mt][nt][2]), "+f"(acc[mt][nt][3])
                        : "r"(af[mt][0]), "r"(af[mt][1]),
                          "r"(af[mt][2]), "r"(af[mt][3]),
                          "r"(bf[nt][0]), "r"(bf[nt][1]));
        }
        __syncthreads();
        buf ^= 1;
    }

    // epilogue
#pragma unroll
    for (int mt = 0; mt < 4; mt++) {
#pragma unroll
        for (int nt = 0; nt < 4; nt++) {
            int row = mb + wm + mt * 16 + g;
            int col = nb + wn + nt * 8 + 2 * tig;
            *(float2*)&C[(size_t)row * N + col] =
                make_float2(acc[mt][nt][0], acc[mt][nt][1]);
            *(float2*)&C[(size_t)(row + 8) * N + col] =
                make_float2(acc[mt][nt][2], acc[mt][nt][3]);
        }
    }
}

// =================================================================
// RoPE cos/sin table (fp32 angle matching jnp, fp64 sincos for accuracy)
// =================================================================
__global__ void rope_table_kernel()
{
    int i = blockIdx.x * blockDim.x + threadIdx.x;
    if (i >= S_LEN * 32) return;
    int pos = i >> 5;
    int f   = i & 31;
    float e    = (float)(2 * f) / 64.0f;
    float pw   = powf(10000.0f, e);
    float invf = 1.0f / pw;
    float angf = (float)pos * invf;
    double s, c;
    sincos((double)angf, &s, &c);
    g_cos[i] = (float)c;
    g_sin[i] = (float)s;
}

// =================================================================
// RoPE apply + optional scale
// =================================================================
__global__ void rope_apply_kernel(float* __restrict__ X, float scale)
{
    int idx = blockIdx.x * blockDim.x + threadIdx.x;
    if (idx >= NTOK * (D_MODEL / 2)) return;
    int tok = idx >> 9;
    int p   = idx & 511;
    int head = p >> 5;
    int fi   = p & 31;
    int pos  = tok & (S_LEN - 1);

    float c = g_cos[pos * 32 + fi];
    float s = g_sin[pos * 32 + fi];

    float2* ptr = (float2*)(X + (size_t)tok * D_MODEL + head * HEAD_DIM + fi * 2);
    float2 v = *ptr;
    float r1 = v.x * c - v.y * s;
    float r2 = v.x * s + v.y * c;
    v.x = r1 * scale;
    v.y = r2 * scale;
    *ptr = v;
}

// =================================================================
// Flash attention, causal (fp32). Unchanged from R0 passing version.
// =================================================================
#define PAD 68
#define ATT_SMEM (4 * 64 * PAD * (int)sizeof(float))

__global__ __launch_bounds__(256) void attn_kernel(
    const float* __restrict__ Q, const float* __restrict__ K,
    const float* __restrict__ V, float* __restrict__ Ctx)
{
    extern __shared__ __align__(16) float sm[];
    float* Qt = sm;
    float* Kt = Qt + 64 * PAD;
    float* Vs = Kt + 64 * PAD;
    float* Ps = Vs + 64 * PAD;

    const int qb = blockIdx.x * 64;
    const int h  = blockIdx.y;
    const int b  = blockIdx.z;

    const int t  = threadIdx.x;
    const int tx = t & 15;
    const int ty = t >> 4;

    const int ljr = t >> 4;
    const int lj  = (t & 15) * 4;

    const float* qbase = Q + ((size_t)b * S_LEN + qb) * D_MODEL + h * HEAD_DIM;

#pragma unroll
    for (int rr = 0; rr < 4; rr++) {
        int r = ljr + rr * 16;
        float4 q4 = *(const float4*)&qbase[(size_t)r * D_MODEL + lj];
        Qt[(lj + 0) * PAD + r] = q4.x;
        Qt[(lj + 1) * PAD + r] = q4.y;
        Qt[(lj + 2) * PAD + r] = q4.z;
        Qt[(lj + 3) * PAD + r] = q4.w;
    }

    float m_[4], l_[4], o_[4][4];
#pragma unroll
    for (int i = 0; i < 4; i++) {
        m_[i] = -1e30f;
        l_[i] = 0.f;
#pragma unroll
        for (int j = 0; j < 4; j++) o_[i][j] = 0.f;
    }

    for (int kt = 0; kt <= qb; kt += 64) {
        const float* kbase = K + ((size_t)b * S_LEN + kt) * D_MODEL + h * HEAD_DIM;
        const float* vbase = V + ((size_t)b * S_LEN + kt) * D_MODEL + h * HEAD_DIM;

        __syncthreads();
#pragma unroll
        for (int rr = 0; rr < 4; rr++) {
            int r = ljr + rr * 16;
            float4 k4 = *(const float4*)&kbase[(size_t)r * D_MODEL + lj];
            Kt[(lj + 0) * PAD + r] = k4.x;
            Kt[(lj + 1) * PAD + r] = k4.y;
            Kt[(lj + 2) * PAD + r] = k4.z;
            Kt[(lj + 3) * PAD + r] = k4.w;
            float4 v4 = *(const float4*)&vbase[(size_t)r * D_MODEL + lj];
            *(float4*)&Vs[r * PAD + lj] = v4;
        }
        __syncthreads();

        float s[4][4];
#pragma unroll
        for (int i = 0; i < 4; i++)
#pragma unroll
            for (int j = 0; j < 4; j++) s[i][j] = 0.f;

#pragma unroll 8
        for (int j = 0; j < 64; j++) {
            float4 av = *(const float4*)&Qt[j * PAD + ty * 4];
            float4 bv = *(const float4*)&Kt[j * PAD + tx * 4];
            float ar[4] = {av.x, av.y, av.z, av.w};
            float br[4] = {bv.x, bv.y, bv.z, bv.w};
#pragma unroll
            for (int i = 0; i < 4; i++)
#pragma unroll
                for (int jj = 0; jj < 4; jj++)
                    s[i][jj] = fmaf(ar[i], br[jj], s[i][jj]);
        }

        if (kt == qb) {
#pragma unroll
            for (int i = 0; i < 4; i++)
#pragma unroll
                for (int jj = 0; jj < 4; jj++)
                    if (tx * 4 + jj > ty * 4 + i) s[i][jj] = -1e30f;
        }

#pragma unroll
        for (int i = 0; i < 4; i++) {
            float rm = fmaxf(fmaxf(s[i][0], s[i][1]), fmaxf(s[i][2], s[i][3]));
#pragma unroll
            for (int off = 1; off < 16; off <<= 1)
                rm = fmaxf(rm, __shfl_xor_sync(0xffffffffu, rm, off));
            float nm = fmaxf(m_[i], rm);
            float alpha = expf(m_[i] - nm);
            float rs = 0.f;
#pragma unroll
            for (int jj = 0; jj < 4; jj++) {
                float p = expf(s[i][jj] - nm);
                s[i][jj] = p;
                rs += p;
            }
#pragma unroll
            for (int off = 1; off < 16; off <<= 1)
                rs += __shfl_xor_sync(0xffffffffu, rs, off);
            l_[i] = l_[i] * alpha + rs;
            m_[i] = nm;
#pragma unroll
            for (int jj = 0; jj < 4; jj++) o_[i][jj] *= alpha;
        }

#pragma unroll
        for (int i = 0; i < 4; i++)
            *(float4*)&Ps[(ty * 4 + i) * PAD + tx * 4] =
                make_float4(s[i][0], s[i][1], s[i][2], s[i][3]);
        __syncthreads();

#pragma unroll 8
        for (int j = 0; j < 64; j++) {
            float4 vv = *(const float4*)&Vs[j * PAD + tx * 4];
#pragma unroll
            for (int i = 0; i < 4; i++) {
                float p = Ps[(ty * 4 + i) * PAD + j];
                o_[i][0] = fmaf(p, vv.x, o_[i][0]);
                o_[i][1] = fmaf(p, vv.y, o_[i][1]);
                o_[i][2] = fmaf(p, vv.z, o_[i][2]);
                o_[i][3] = fmaf(p, vv.w, o_[i][3]);
            }
        }
    }

    float* cbase = Ctx + ((size_t)b * S_LEN + qb) * D_MODEL + h * HEAD_DIM;
#pragma unroll
    for (int i = 0; i < 4; i++) {
        float inv = 1.0f / l_[i];
        float4 o = make_float4(o_[i][0] * inv, o_[i][1] * inv,
                               o_[i][2] * inv, o_[i][3] * inv);
        *(float4*)&cbase[(size_t)(ty * 4 + i) * D_MODEL + tx * 4] = o;
    }
}

// =================================================================
// Launch
// =================================================================
extern "C" void kernel_launch(void* const* d_in, const int* in_sizes, int n_in,
                              void* d_out, int out_size)
{
    const float* x  = (const float*)d_in[0];
    const float* Wq = (const float*)d_in[1];
    const float* Wk = (const float*)d_in[2];
    const float* Wv = (const float*)d_in[3];
    const float* Wo = (const float*)d_in[4];
    float* out = (float*)d_out;

    float *Q, *K, *V, *C;
    cudaGetSymbolAddress((void**)&Q, g_Q);
    cudaGetSymbolAddress((void**)&K, g_K);
    cudaGetSymbolAddress((void**)&V, g_V);
    cudaGetSymbolAddress((void**)&C, g_C);

    dim3 gemm_grid(D_MODEL / 128, NTOK / 128);   // (8, 32)

    // QKV projections (tf32 tensor cores)
    gemm_tf32<<<gemm_grid, 256>>>(x, Wq, Q, NTOK, D_MODEL, D_MODEL);
    gemm_tf32<<<gemm_grid, 256>>>(x, Wk, K, NTOK, D_MODEL, D_MODEL);
    gemm_tf32<<<gemm_grid, 256>>>(x, Wv, V, NTOK, D_MODEL, D_MODEL);

    // RoPE
    rope_table_kernel<<<(S_LEN * 32 + 255) / 256, 256>>>();
    int rope_threads = NTOK * (D_MODEL / 2);
    rope_apply_kernel<<<(rope_threads + 255) / 256, 256>>>(Q, 0.125f);
    rope_apply_kernel<<<(rope_threads + 255) / 256, 256>>>(K, 1.0f);

    // attention (fp32)
    cudaFuncSetAttribute(attn_kernel, cudaFuncAttributeMaxDynamicSharedMemorySize, ATT_SMEM);
    attn_kernel<<<dim3(S_LEN / 64, N_HEADS, BATCH), 256, ATT_SMEM>>>(Q, K, V, C);

    // output projection
    gemm_tf32<<<gemm_grid, 256>>>(C, Wo, out, NTOK, D_MODEL, D_MODEL);
}

// round 3
// speedup vs baseline: 2.9402x; 1.8234x over previous
#include <cuda_runtime.h>
#include <math.h>

#define S_LEN    2048
#define D_MODEL  1024
#define N_HEADS  16
#define HEAD_DIM 64
#define BATCH    2
#define NTOK     (BATCH * S_LEN)   // 4096

// -------- scratch (device globals: no allocations allowed) --------
__device__ float g_Q[NTOK * D_MODEL];
__device__ float g_K[NTOK * D_MODEL];
__device__ float g_V[NTOK * D_MODEL];
__device__ float g_C[NTOK * D_MODEL];
__device__ float g_cos[S_LEN * 32];
__device__ float g_sin[S_LEN * 32];

__device__ __forceinline__ unsigned f2tf(float x) {
    unsigned u;
    asm("cvt.rna.tf32.f32 %0, %1;" : "=r"(u) : "f"(x));
    return u;
}

__device__ __forceinline__ void mma8(float c[4], const unsigned a[4],
                                     unsigned b0, unsigned b1) {
    asm volatile(
        "mma.sync.aligned.m16n8k8.row.col.f32.tf32.tf32.f32 "
        "{%0,%1,%2,%3},{%4,%5,%6,%7},{%8,%9},{%0,%1,%2,%3};"
        : "+f"(c[0]), "+f"(c[1]), "+f"(c[2]), "+f"(c[3])
        : "r"(a[0]), "r"(a[1]), "r"(a[2]), "r"(a[3]), "r"(b0), "r"(b1));
}

// =================================================================
// TF32 tensor-core GEMM: C[M,N] = A[M,K] @ B[N,K]^T  (unchanged, passing)
// =================================================================
#define AST 20

__global__ __launch_bounds__(256, 2) void gemm_tf32(
    const float* __restrict__ A, const float* __restrict__ B,
    float* __restrict__ C, int M, int N, int K)
{
    __shared__ __align__(16) float As[2][128 * AST];
    __shared__ __align__(16) float Bs[2][128 * AST];

    const int t    = threadIdx.x;
    const int warp = t >> 5, lane = t & 31;
    const int g    = lane >> 2, tig = lane & 3;
    const int wm   = (warp >> 2) * 64;
    const int wn   = (warp & 3) * 32;
    const int mb   = blockIdx.y * 128;
    const int nb   = blockIdx.x * 128;

    float acc[4][4][4];
#pragma unroll
    for (int mt = 0; mt < 4; mt++)
#pragma unroll
        for (int nt = 0; nt < 4; nt++)
#pragma unroll
            for (int i = 0; i < 4; i++) acc[mt][nt][i] = 0.f;

#define LOAD_STAGE(buf, kt)                                                        \
    do {                                                                           \
        _Pragma("unroll")                                                          \
        for (int i = 0; i < 2; i++) {                                              \
            int idx = t + i * 256;                                                 \
            int row = idx >> 2, col = (idx & 3) * 4;                               \
            unsigned da = (unsigned)__cvta_generic_to_shared(                      \
                &As[buf][row * AST + col]);                                        \
            const float* ga = A + (size_t)(mb + row) * K + (kt) + col;             \
            asm volatile("cp.async.cg.shared.global [%0], [%1], 16;"               \
                         :: "r"(da), "l"(ga));                                     \
            unsigned db = (unsigned)__cvta_generic_to_shared(                      \
                &Bs[buf][row * AST + col]);                                        \
            const float* gb = B + (size_t)(nb + row) * K + (kt) + col;             \
            asm volatile("cp.async.cg.shared.global [%0], [%1], 16;"               \
                         :: "r"(db), "l"(gb));                                     \
        }                                                                          \
        asm volatile("cp.async.commit_group;");                                    \
    } while (0)

    int buf = 0;
    LOAD_STAGE(0, 0);

    for (int kt = 0; kt < K; kt += 16) {
        asm volatile("cp.async.wait_group 0;");
        __syncthreads();
        if (kt + 16 < K) LOAD_STAGE(buf ^ 1, kt + 16);

        const float* Ab = As[buf];
        const float* Bb = Bs[buf];

#pragma unroll
        for (int ks = 0; ks < 2; ks++) {
            const int kb = ks * 8;
            unsigned af[4][4], bf[4][2];
#pragma unroll
            for (int mt = 0; mt < 4; mt++) {
                int r0 = wm + mt * 16 + g;
                af[mt][0] = f2tf(Ab[r0 * AST + kb + tig]);
                af[mt][1] = f2tf(Ab[(r0 + 8) * AST + kb + tig]);
                af[mt][2] = f2tf(Ab[r0 * AST + kb + tig + 4]);
                af[mt][3] = f2tf(Ab[(r0 + 8) * AST + kb + tig + 4]);
            }
#pragma unroll
            for (int nt = 0; nt < 4; nt++) {
                int n0 = wn + nt * 8 + g;
                bf[nt][0] = f2tf(Bb[n0 * AST + kb + tig]);
                bf[nt][1] = f2tf(Bb[n0 * AST + kb + tig + 4]);
            }
#pragma unroll
            for (int mt = 0; mt < 4; mt++)
#pragma unroll
                for (int nt = 0; nt < 4; nt++)
                    mma8(acc[mt][nt], af[mt], bf[nt][0], bf[nt][1]);
        }
        __syncthreads();
        buf ^= 1;
    }

#pragma unroll
    for (int mt = 0; mt < 4; mt++) {
#pragma unroll
        for (int nt = 0; nt < 4; nt++) {
            int row = mb + wm + mt * 16 + g;
            int col = nb + wn + nt * 8 + 2 * tig;
            *(float2*)&C[(size_t)row * N + col] =
                make_float2(acc[mt][nt][0], acc[mt][nt][1]);
            *(float2*)&C[(size_t)(row + 8) * N + col] =
                make_float2(acc[mt][nt][2], acc[mt][nt][3]);
        }
    }
}

// =================================================================
// RoPE table (fp32 angle matching jnp, fp64 sincos)
// =================================================================
__global__ void rope_table_kernel()
{
    int i = blockIdx.x * blockDim.x + threadIdx.x;
    if (i >= S_LEN * 32) return;
    int pos = i >> 5;
    int f   = i & 31;
    float e    = (float)(2 * f) / 64.0f;
    float pw   = powf(10000.0f, e);
    float invf = 1.0f / pw;
    float angf = (float)pos * invf;
    double s, c;
    sincos((double)angf, &s, &c);
    g_cos[i] = (float)c;
    g_sin[i] = (float)s;
}

// =================================================================
// RoPE apply for Q (scaled by 0.125) and K in ONE launch
// =================================================================
__global__ void rope_apply2_kernel(float* __restrict__ Qp, float* __restrict__ Kp)
{
    int idx = blockIdx.x * blockDim.x + threadIdx.x;
    const int n = NTOK * (D_MODEL / 2);
    float* X;
    float scale;
    if (idx < n) { X = Qp; scale = 0.125f; }
    else         { X = Kp; scale = 1.0f; idx -= n; }

    int tok = idx >> 9;
    int p   = idx & 511;
    int head = p >> 5;
    int fi   = p & 31;
    int pos  = tok & (S_LEN - 1);

    float c = g_cos[pos * 32 + fi];
    float s = g_sin[pos * 32 + fi];

    float2* ptr = (float2*)(X + (size_t)tok * D_MODEL + head * HEAD_DIM + fi * 2);
    float2 v = *ptr;
    float r1 = v.x * c - v.y * s;
    float r2 = v.x * s + v.y * c;
    v.x = r1 * scale;
    v.y = r2 * scale;
    *ptr = v;
}

// =================================================================
// TF32 flash attention, causal.
// CTA: 128 q-rows x (k-tiles of 64). 8 warps, warp w = rows [16w,16w+16).
// smem: Ks[64][72], Vs[64][72], Ps[128][72] (doubles as Q staging).
// All values in smem are pre-rounded to tf32 bit patterns.
// =================================================================
#define ST 72
#define ATT_SMEM2 ((64 * ST + 64 * ST + 128 * ST) * (int)sizeof(float))

__global__ __launch_bounds__(256, 2) void attn_tf32(
    const float* __restrict__ Q, const float* __restrict__ K,
    const float* __restrict__ V, float* __restrict__ Ctx)
{
    extern __shared__ __align__(16) float sm2[];
    float* Ks = sm2;
    float* Vs = sm2 + 64 * ST;
    float* Ps = sm2 + 128 * ST;

    const int t = threadIdx.x, warp = t >> 5, lane = t & 31;
    const int g = lane >> 2, tig = lane & 3;
    const int qb = blockIdx.x * 128;
    const int h  = blockIdx.y, b = blockIdx.z;

    const float* Qg = Q + ((size_t)b * S_LEN + qb) * D_MODEL + h * HEAD_DIM;

    // ---- stage Q (128x64) into Ps (coalesced), tf32-rounded ----
#pragma unroll
    for (int i = 0; i < 8; i++) {
        int idx = t + i * 256;            // 0..2047
        int row = idx >> 4, c4 = (idx & 15) * 4;
        float4 q4 = *(const float4*)&Qg[(size_t)row * D_MODEL + c4];
        float4 r;
        r.x = __uint_as_float(f2tf(q4.x));
        r.y = __uint_as_float(f2tf(q4.y));
        r.z = __uint_as_float(f2tf(q4.z));
        r.w = __uint_as_float(f2tf(q4.w));
        *(float4*)&Ps[row * ST + c4] = r;
    }
    __syncthreads();

    // ---- read Q A-fragments into registers (warp-private rows) ----
    unsigned qf[8][4];
#pragma unroll
    for (int kc = 0; kc < 8; kc++) {
        qf[kc][0] = __float_as_uint(Ps[(warp * 16 + g) * ST + kc * 8 + tig]);
        qf[kc][1] = __float_as_uint(Ps[(warp * 16 + g + 8) * ST + kc * 8 + tig]);
        qf[kc][2] = __float_as_uint(Ps[(warp * 16 + g) * ST + kc * 8 + tig + 4]);
        qf[kc][3] = __float_as_uint(Ps[(warp * 16 + g + 8) * ST + kc * 8 + tig + 4]);
    }

    float m0 = -1e30f, m1 = -1e30f, l0 = 0.f, l1 = 0.f;
    float o[8][4];
#pragma unroll
    for (int nt = 0; nt < 8; nt++)
#pragma unroll
        for (int i = 0; i < 4; i++) o[nt][i] = 0.f;

    const int r0 = qb + warp * 16 + g;
    const int r1 = r0 + 8;
    const int wrow_max = qb + warp * 16 + 15;

    for (int kt = 0; kt <= qb + 64; kt += 64) {
        __syncthreads();   // previous iter's Ks/Vs reads complete
        const float* Kg = K + ((size_t)b * S_LEN + kt) * D_MODEL + h * HEAD_DIM;
        const float* Vg = V + ((size_t)b * S_LEN + kt) * D_MODEL + h * HEAD_DIM;
#pragma unroll
        for (int i = 0; i < 4; i++) {
            int idx = t + i * 256;        // 0..1023
            int row = idx >> 4, c4 = (idx & 15) * 4;
            float4 k4 = *(const float4*)&Kg[(size_t)row * D_MODEL + c4];
            float4 v4 = *(const float4*)&Vg[(size_t)row * D_MODEL + c4];
            float4 rk, rv;
            rk.x = __uint_as_float(f2tf(k4.x));
            rk.y = __uint_as_float(f2tf(k4.y));
            rk.z = __uint_as_float(f2tf(k4.z));
            rk.w = __uint_as_float(f2tf(k4.w));
            rv.x = __uint_as_float(f2tf(v4.x));
            rv.y = __uint_as_float(f2tf(v4.y));
            rv.z = __uint_as_float(f2tf(v4.z));
            rv.w = __uint_as_float(f2tf(v4.w));
            *(float4*)&Ks[row * ST + c4] = rk;
            *(float4*)&Vs[row * ST + c4] = rv;
        }
        __syncthreads();

        if (kt > wrow_max) continue;   // tile fully masked for this warp

        // ---- S = Q K^T ----
        float s[8][4];
#pragma unroll
        for (int nt = 0; nt < 8; nt++) {
            float c[4] = {0.f, 0.f, 0.f, 0.f};
#pragma unroll
            for (int kc = 0; kc < 8; kc++) {
                unsigned b0 = __float_as_uint(Ks[(nt * 8 + g) * ST + kc * 8 + tig]);
                unsigned b1 = __float_as_uint(Ks[(nt * 8 + g) * ST + kc * 8 + tig + 4]);
                mma8(c, qf[kc], b0, b1);
            }
            s[nt][0] = c[0]; s[nt][1] = c[1]; s[nt][2] = c[2]; s[nt][3] = c[3];
        }

        // ---- causal mask (diagonal tiles only) ----
        if (kt + 63 > qb + warp * 16) {
#pragma unroll
            for (int nt = 0; nt < 8; nt++) {
                int k0 = kt + nt * 8 + 2 * tig;
                if (k0 > r0)     s[nt][0] = -1e30f;
                if (k0 + 1 > r0) s[nt][1] = -1e30f;
                if (k0 > r1)     s[nt][2] = -1e30f;
                if (k0 + 1 > r1) s[nt][3] = -1e30f;
            }
        }

        // ---- online softmax ----
        float mx0 = -1e30f, mx1 = -1e30f;
#pragma unroll
        for (int nt = 0; nt < 8; nt++) {
            mx0 = fmaxf(mx0, fmaxf(s[nt][0], s[nt][1]));
            mx1 = fmaxf(mx1, fmaxf(s[nt][2], s[nt][3]));
        }
        mx0 = fmaxf(mx0, __shfl_xor_sync(0xffffffffu, mx0, 1));
        mx0 = fmaxf(mx0, __shfl_xor_sync(0xffffffffu, mx0, 2));
        mx1 = fmaxf(mx1, __shfl_xor_sync(0xffffffffu, mx1, 1));
        mx1 = fmaxf(mx1, __shfl_xor_sync(0xffffffffu, mx1, 2));

        float nm0 = fmaxf(m0, mx0), nm1 = fmaxf(m1, mx1);
        float a0 = __expf(m0 - nm0), a1 = __expf(m1 - nm1);
        float sum0 = 0.f, sum1 = 0.f;
#pragma unroll
        for (int nt = 0; nt < 8; nt++) {
            s[nt][0] = __expf(s[nt][0] - nm0);
            s[nt][1] = __expf(s[nt][1] - nm0);
            s[nt][2] = __expf(s[nt][2] - nm1);
            s[nt][3] = __expf(s[nt][3] - nm1);
            sum0 += s[nt][0] + s[nt][1];
            sum1 += s[nt][2] + s[nt][3];
        }
        sum0 += __shfl_xor_sync(0xffffffffu, sum0, 1);
        sum0 += __shfl_xor_sync(0xffffffffu, sum0, 2);
        sum1 += __shfl_xor_sync(0xffffffffu, sum1, 1);
        sum1 += __shfl_xor_sync(0xffffffffu, sum1, 2);

        l0 = l0 * a0 + sum0;
        l1 = l1 * a1 + sum1;
        m0 = nm0; m1 = nm1;
#pragma unroll
        for (int nt = 0; nt < 8; nt++) {
            o[nt][0] *= a0; o[nt][1] *= a0;
            o[nt][2] *= a1; o[nt][3] *= a1;
        }

        // ---- store P (tf32 bits) to warp-private Ps rows ----
#pragma unroll
        for (int nt = 0; nt < 8; nt++) {
            *(float2*)&Ps[(warp * 16 + g) * ST + nt * 8 + 2 * tig] =
                make_float2(__uint_as_float(f2tf(s[nt][0])),
                            __uint_as_float(f2tf(s[nt][1])));
            *(float2*)&Ps[(warp * 16 + g + 8) * ST + nt * 8 + 2 * tig] =
                make_float2(__uint_as_float(f2tf(s[nt][2])),
                            __uint_as_float(f2tf(s[nt][3])));
        }
        __syncwarp();

        // ---- O += P @ V ----
#pragma unroll
        for (int kc = 0; kc < 8; kc++) {
            unsigned pf[4];
            pf[0] = __float_as_uint(Ps[(warp * 16 + g) * ST + kc * 8 + tig]);
            pf[1] = __float_as_uint(Ps[(warp * 16 + g + 8) * ST + kc * 8 + tig]);
            pf[2] = __float_as_uint(Ps[(warp * 16 + g) * ST + kc * 8 + tig + 4]);
            pf[3] = __float_as_uint(Ps[(warp * 16 + g + 8) * ST + kc * 8 + tig + 4]);
#pragma unroll
            for (int nt = 0; nt < 8; nt++) {
                unsigned b0 = __float_as_uint(Vs[(kc * 8 + tig) * ST + nt * 8 + g]);
                unsigned b1 = __float_as_uint(Vs[(kc * 8 + tig + 4) * ST + nt * 8 + g]);
                mma8(o[nt], pf, b0, b1);
            }
        }
        __syncwarp();   // Ps reads done before next iteration's stores
    }

    // ---- epilogue ----
    float inv0 = 1.0f / l0, inv1 = 1.0f / l1;
    float* Cb = Ctx + ((size_t)b * S_LEN + qb + warp * 16) * D_MODEL + h * HEAD_DIM;
#pragma unroll
    for (int nt = 0; nt < 8; nt++) {
        *(float2*)&Cb[(size_t)g * D_MODEL + nt * 8 + 2 * tig] =
            make_float2(o[nt][0] * inv0, o[nt][1] * inv0);
        *(float2*)&Cb[(size_t)(g + 8) * D_MODEL + nt * 8 + 2 * tig] =
            make_float2(o[nt][2] * inv1, o[nt][3] * inv1);
    }
}

// =================================================================
// Launch
// =================================================================
extern "C" void kernel_launch(void* const* d_in, const int* in_sizes, int n_in,
                              void* d_out, int out_size)
{
    const float* x  = (const float*)d_in[0];
    const float* Wq = (const float*)d_in[1];
    const float* Wk = (const float*)d_in[2];
    const float* Wv = (const float*)d_in[3];
    const float* Wo = (const float*)d_in[4];
    float* out = (float*)d_out;

    float *Q, *K, *V, *C;
    cudaGetSymbolAddress((void**)&Q, g_Q);
    cudaGetSymbolAddress((void**)&K, g_K);
    cudaGetSymbolAddress((void**)&V, g_V);
    cudaGetSymbolAddress((void**)&C, g_C);

    dim3 gemm_grid(D_MODEL / 128, NTOK / 128);   // (8, 32)

    // launch 0: rope table (no deps)
    rope_table_kernel<<<(S_LEN * 32 + 255) / 256, 256>>>();

    // launches 1-3: QKV projections
    gemm_tf32<<<gemm_grid, 256>>>(x, Wq, Q, NTOK, D_MODEL, D_MODEL);
    gemm_tf32<<<gemm_grid, 256>>>(x, Wk, K, NTOK, D_MODEL, D_MODEL);
    gemm_tf32<<<gemm_grid, 256>>>(x, Wv, V, NTOK, D_MODEL, D_MODEL);

    // launch 4: RoPE (Q scaled + K) in one kernel
    int rope_threads = 2 * NTOK * (D_MODEL / 2);
    rope_apply2_kernel<<<(rope_threads + 255) / 256, 256>>>(Q, K);

    // launch 5: attention (tf32 tensor cores)  <- ncu -s 5 lands here
    cudaFuncSetAttribute(attn_tf32, cudaFuncAttributeMaxDynamicSharedMemorySize, ATT_SMEM2);
    attn_tf32<<<dim3(S_LEN / 128, N_HEADS, BATCH), 256, ATT_SMEM2>>>(Q, K, V, C);

    // launch 6: output projection
    gemm_tf32<<<gemm_grid, 256>>>(C, Wo, out, NTOK, D_MODEL, D_MODEL);
}

// round 4
// speedup vs baseline: 3.0696x; 1.0440x over previous
#include <cuda_runtime.h>
#include <math.h>

#define S_LEN    2048
#define D_MODEL  1024
#define N_HEADS  16
#define HEAD_DIM 64
#define BATCH    2
#define NTOK     (BATCH * S_LEN)   // 4096

// -------- scratch (device globals: no allocations allowed) --------
__device__ float g_Q[NTOK * D_MODEL];
__device__ float g_K[NTOK * D_MODEL];
__device__ float g_V[NTOK * D_MODEL];
__device__ float g_C[NTOK * D_MODEL];
__device__ float g_Xr[NTOK * D_MODEL];            // tf32-rounded x
__device__ float g_Wr[4][D_MODEL * D_MODEL];      // tf32-rounded Wq,Wk,Wv,Wo
__device__ float g_cos[S_LEN * 32];
__device__ float g_sin[S_LEN * 32];

__device__ __forceinline__ unsigned f2tf(float x) {
    unsigned u;
    asm("cvt.rna.tf32.f32 %0, %1;" : "=r"(u) : "f"(x));
    return u;
}
__device__ __forceinline__ float f2tff(float x) { return __uint_as_float(f2tf(x)); }

__device__ __forceinline__ void mma8(float c[4], const unsigned a[4],
                                     unsigned b0, unsigned b1) {
    asm volatile(
        "mma.sync.aligned.m16n8k8.row.col.f32.tf32.tf32.f32 "
        "{%0,%1,%2,%3},{%4,%5,%6,%7},{%8,%9},{%0,%1,%2,%3};"
        : "+f"(c[0]), "+f"(c[1]), "+f"(c[2]), "+f"(c[3])
        : "r"(a[0]), "r"(a[1]), "r"(a[2]), "r"(a[3]), "r"(b0), "r"(b1));
}

// =================================================================
// Pre-round x and the four weights to tf32-valued fp32 (one pass).
// =================================================================
__global__ void preround_kernel(const float* __restrict__ x,
                                const float* __restrict__ Wq,
                                const float* __restrict__ Wk,
                                const float* __restrict__ Wv,
                                const float* __restrict__ Wo)
{
    const int NX = NTOK * D_MODEL / 4;       // 1M float4
    const int NW = D_MODEL * D_MODEL / 4;    // 256K float4
    int i = blockIdx.x * blockDim.x + threadIdx.x;
    const float4* src;
    float4* dst;
    if (i < NX) { src = (const float4*)x; dst = (float4*)g_Xr; }
    else {
        int j = i - NX;
        int w = j / NW;
        i = j - w * NW;
        const float* ws[4] = {Wq, Wk, Wv, Wo};
        src = (const float4*)ws[w];
        dst = (float4*)g_Wr[w];
    }
    float4 v = src[i];
    v.x = f2tff(v.x); v.y = f2tff(v.y); v.z = f2tff(v.z); v.w = f2tff(v.w);
    dst[i] = v;
}

// =================================================================
// RoPE table (fp32 angle matching jnp, fp64 sincos)
// =================================================================
__global__ void rope_table_kernel()
{
    int i = blockIdx.x * blockDim.x + threadIdx.x;
    if (i >= S_LEN * 32) return;
    int pos = i >> 5;
    int f   = i & 31;
    float e    = (float)(2 * f) / 64.0f;
    float pw   = powf(10000.0f, e);
    float invf = 1.0f / pw;
    float angf = (float)pos * invf;
    double s, c;
    sincos((double)angf, &s, &c);
    g_cos[i] = (float)c;
    g_sin[i] = (float)s;
}

// =================================================================
// TF32 GEMM core: C[M,N] = A[M,K] @ B[N,K]^T, inputs pre-rounded.
// 128x128x16 tile, 256 thr, 3-stage cp.async, optional RoPE epilogue.
// rope_mode: 0 = none, 1 = rope (scale applied after rotation)
// =================================================================
#define AST 20

__device__ __forceinline__ void gemm_body(
    const float* __restrict__ A, const float* __restrict__ B,
    float* __restrict__ C, int M, int N, int K,
    int mb, int nb, int rope_mode, float scale)
{
    __shared__ __align__(16) float As[3][128 * AST];
    __shared__ __align__(16) float Bs[3][128 * AST];

    const int t    = threadIdx.x;
    const int warp = t >> 5, lane = t & 31;
    const int g    = lane >> 2, tig = lane & 3;
    const int wm   = (warp >> 2) * 64;
    const int wn   = (warp & 3) * 32;

    float acc[4][4][4];
#pragma unroll
    for (int mt = 0; mt < 4; mt++)
#pragma unroll
        for (int nt = 0; nt < 4; nt++)
#pragma unroll
            for (int i = 0; i < 4; i++) acc[mt][nt][i] = 0.f;

    const int lrow = t >> 2, lcol = (t & 3) * 4;

#define LOAD_STAGE3(buf, kt)                                                       \
    do {                                                                           \
        unsigned da = (unsigned)__cvta_generic_to_shared(                          \
            &As[buf][lrow * AST + lcol]);                                          \
        const float* ga = A + (size_t)(mb + lrow) * K + (kt) + lcol;               \
        asm volatile("cp.async.cg.shared.global [%0], [%1], 16;"                   \
                     :: "r"(da), "l"(ga));                                         \
        unsigned db = (unsigned)__cvta_generic_to_shared(                          \
            &Bs[buf][lrow * AST + lcol]);                                          \
        const float* gb = B + (size_t)(nb + lrow) * K + (kt) + lcol;               \
        asm volatile("cp.async.cg.shared.global [%0], [%1], 16;"                   \
                     :: "r"(db), "l"(gb));                                         \
        unsigned da2 = (unsigned)__cvta_generic_to_shared(                         \
            &As[buf][(lrow + 64) * AST + lcol]);                                   \
        const float* ga2 = A + (size_t)(mb + lrow + 64) * K + (kt) + lcol;         \
        asm volatile("cp.async.cg.shared.global [%0], [%1], 16;"                   \
                     :: "r"(da2), "l"(ga2));                                       \
        unsigned db2 = (unsigned)__cvta_generic_to_shared(                         \
            &Bs[buf][(lrow + 64) * AST + lcol]);                                   \
        const float* gb2 = B + (size_t)(nb + lrow + 64) * K + (kt) + lcol;         \
        asm volatile("cp.async.cg.shared.global [%0], [%1], 16;"                   \
                     :: "r"(db2), "l"(gb2));                                       \
        asm volatile("cp.async.commit_group;");                                    \
    } while (0)

    const int NIT = K / 16;   // 64
    LOAD_STAGE3(0, 0);
    LOAD_STAGE3(1, 16);

    for (int i = 0; i < NIT; i++) {
        asm volatile("cp.async.wait_group 1;");
        __syncthreads();
        if (i + 2 < NIT) {
            int nbuf = (i + 2) % 3;
            LOAD_STAGE3(nbuf, (i + 2) * 16);
        }
        const float* Ab = As[i % 3];
        const float* Bb = Bs[i % 3];

#pragma unroll
        for (int ks = 0; ks < 2; ks++) {
            const int kb = ks * 8;
            unsigned af[4][4], bf[4][2];
#pragma unroll
            for (int mt = 0; mt < 4; mt++) {
                int r0 = wm + mt * 16 + g;
                af[mt][0] = __float_as_uint(Ab[r0 * AST + kb + tig]);
                af[mt][1] = __float_as_uint(Ab[(r0 + 8) * AST + kb + tig]);
                af[mt][2] = __float_as_uint(Ab[r0 * AST + kb + tig + 4]);
                af[mt][3] = __float_as_uint(Ab[(r0 + 8) * AST + kb + tig + 4]);
            }
#pragma unroll
            for (int nt = 0; nt < 4; nt++) {
                int n0 = wn + nt * 8 + g;
                bf[nt][0] = __float_as_uint(Bb[n0 * AST + kb + tig]);
                bf[nt][1] = __float_as_uint(Bb[n0 * AST + kb + tig + 4]);
            }
#pragma unroll
            for (int mt = 0; mt < 4; mt++)
#pragma unroll
                for (int nt = 0; nt < 4; nt++)
                    mma8(acc[mt][nt], af[mt], bf[nt][0], bf[nt][1]);
        }
        __syncthreads();
    }

    // ---- epilogue (optionally fused RoPE) ----
#pragma unroll
    for (int mt = 0; mt < 4; mt++) {
#pragma unroll
        for (int nt = 0; nt < 4; nt++) {
            int row = mb + wm + mt * 16 + g;
            int col = nb + wn + nt * 8 + 2 * tig;
            float v0 = acc[mt][nt][0], v1 = acc[mt][nt][1];
            float v2 = acc[mt][nt][2], v3 = acc[mt][nt][3];
            if (rope_mode) {
                int fi = (col & 63) >> 1;
                int p0 = row & (S_LEN - 1);
                int p1 = (row + 8) & (S_LEN - 1);
                float c0 = g_cos[p0 * 32 + fi], s0 = g_sin[p0 * 32 + fi];
                float c1 = g_cos[p1 * 32 + fi], s1 = g_sin[p1 * 32 + fi];
                float r0 = v0 * c0 - v1 * s0, r1 = v0 * s0 + v1 * c0;
                float r2 = v2 * c1 - v3 * s1, r3 = v2 * s1 + v3 * c1;
                v0 = r0 * scale; v1 = r1 * scale;
                v2 = r2 * scale; v3 = r3 * scale;
            }
            *(float2*)&C[(size_t)row * N + col] = make_float2(v0, v1);
            *(float2*)&C[(size_t)(row + 8) * N + col] = make_float2(v2, v3);
        }
    }
}

// fused QKV: grid.z selects weight/output; RoPE fused for Q (scaled) and K
__global__ __launch_bounds__(256, 2) void qkv_gemm_kernel(const float* __restrict__ A)
{
    const int z = blockIdx.z;
    float* outs[3] = {g_Q, g_K, g_V};
    const float* B = g_Wr[z];
    float* C = outs[z];
    int rope_mode = (z < 2) ? 1 : 0;
    float scale = (z == 0) ? 0.125f : 1.0f;
    gemm_body(A, B, C, NTOK, D_MODEL, D_MODEL,
              blockIdx.y * 128, blockIdx.x * 128, rope_mode, scale);
}

__global__ __launch_bounds__(256, 2) void out_gemm_kernel(float* __restrict__ out)
{
    gemm_body(g_C, g_Wr[3], out, NTOK, D_MODEL, D_MODEL,
              blockIdx.y * 128, blockIdx.x * 128, 0, 1.0f);
}

// =================================================================
// TF32 flash attention, causal (unchanged core; epilogue rounds C to tf32)
// =================================================================
#define ST 72
#define ATT_SMEM2 ((64 * ST + 64 * ST + 128 * ST) * (int)sizeof(float))

__global__ __launch_bounds__(256, 2) void attn_tf32(
    const float* __restrict__ Q, const float* __restrict__ K,
    const float* __restrict__ V, float* __restrict__ Ctx)
{
    extern __shared__ __align__(16) float sm2[];
    float* Ks = sm2;
    float* Vs = sm2 + 64 * ST;
    float* Ps = sm2 + 128 * ST;

    const int t = threadIdx.x, warp = t >> 5, lane = t & 31;
    const int g = lane >> 2, tig = lane & 3;
    const int qb = blockIdx.x * 128;
    const int h  = blockIdx.y, b = blockIdx.z;

    const float* Qg = Q + ((size_t)b * S_LEN + qb) * D_MODEL + h * HEAD_DIM;

#pragma unroll
    for (int i = 0; i < 8; i++) {
        int idx = t + i * 256;
        int row = idx >> 4, c4 = (idx & 15) * 4;
        float4 q4 = *(const float4*)&Qg[(size_t)row * D_MODEL + c4];
        float4 r;
        r.x = f2tff(q4.x); r.y = f2tff(q4.y);
        r.z = f2tff(q4.z); r.w = f2tff(q4.w);
        *(float4*)&Ps[row * ST + c4] = r;
    }
    __syncthreads();

    unsigned qf[8][4];
#pragma unroll
    for (int kc = 0; kc < 8; kc++) {
        qf[kc][0] = __float_as_uint(Ps[(warp * 16 + g) * ST + kc * 8 + tig]);
        qf[kc][1] = __float_as_uint(Ps[(warp * 16 + g + 8) * ST + kc * 8 + tig]);
        qf[kc][2] = __float_as_uint(Ps[(warp * 16 + g) * ST + kc * 8 + tig + 4]);
        qf[kc][3] = __float_as_uint(Ps[(warp * 16 + g + 8) * ST + kc * 8 + tig + 4]);
    }

    float m0 = -1e30f, m1 = -1e30f, l0 = 0.f, l1 = 0.f;
    float o[8][4];
#pragma unroll
    for (int nt = 0; nt < 8; nt++)
#pragma unroll
        for (int i = 0; i < 4; i++) o[nt][i] = 0.f;

    const int r0 = qb + warp * 16 + g;
    const int r1 = r0 + 8;
    const int wrow_max = qb + warp * 16 + 15;

    for (int kt = 0; kt <= qb + 64; kt += 64) {
        __syncthreads();
        const float* Kg = K + ((size_t)b * S_LEN + kt) * D_MODEL + h * HEAD_DIM;
        const float* Vg = V + ((size_t)b * S_LEN + kt) * D_MODEL + h * HEAD_DIM;
#pragma unroll
        for (int i = 0; i < 4; i++) {
            int idx = t + i * 256;
            int row = idx >> 4, c4 = (idx & 15) * 4;
            float4 k4 = *(const float4*)&Kg[(size_t)row * D_MODEL + c4];
            float4 v4 = *(const float4*)&Vg[(size_t)row * D_MODEL + c4];
            float4 rk, rv;
            rk.x = f2tff(k4.x); rk.y = f2tff(k4.y);
            rk.z = f2tff(k4.z); rk.w = f2tff(k4.w);
            rv.x = f2tff(v4.x); rv.y = f2tff(v4.y);
            rv.z = f2tff(v4.z); rv.w = f2tff(v4.w);
            *(float4*)&Ks[row * ST + c4] = rk;
            *(float4*)&Vs[row * ST + c4] = rv;
        }
        __syncthreads();

        if (kt > wrow_max) continue;

        float s[8][4];
#pragma unroll
        for (int nt = 0; nt < 8; nt++) {
            float c[4] = {0.f, 0.f, 0.f, 0.f};
#pragma unroll
            for (int kc = 0; kc < 8; kc++) {
                unsigned b0 = __float_as_uint(Ks[(nt * 8 + g) * ST + kc * 8 + tig]);
                unsigned b1 = __float_as_uint(Ks[(nt * 8 + g) * ST + kc * 8 + tig + 4]);
                mma8(c, qf[kc], b0, b1);
            }
            s[nt][0] = c[0]; s[nt][1] = c[1]; s[nt][2] = c[2]; s[nt][3] = c[3];
        }

        if (kt + 63 > qb + warp * 16) {
#pragma unroll
            for (int nt = 0; nt < 8; nt++) {
                int k0 = kt + nt * 8 + 2 * tig;
                if (k0 > r0)     s[nt][0] = -1e30f;
                if (k0 + 1 > r0) s[nt][1] = -1e30f;
                if (k0 > r1)     s[nt][2] = -1e30f;
                if (k0 + 1 > r1) s[nt][3] = -1e30f;
            }
        }

        float mx0 = -1e30f, mx1 = -1e30f;
#pragma unroll
        for (int nt = 0; nt < 8; nt++) {
            mx0 = fmaxf(mx0, fmaxf(s[nt][0], s[nt][1]));
            mx1 = fmaxf(mx1, fmaxf(s[nt][2], s[nt][3]));
        }
        mx0 = fmaxf(mx0, __shfl_xor_sync(0xffffffffu, mx0, 1));
        mx0 = fmaxf(mx0, __shfl_xor_sync(0xffffffffu, mx0, 2));
        mx1 = fmaxf(mx1, __shfl_xor_sync(0xffffffffu, mx1, 1));
        mx1 = fmaxf(mx1, __shfl_xor_sync(0xffffffffu, mx1, 2));

        float nm0 = fmaxf(m0, mx0), nm1 = fmaxf(m1, mx1);
        float a0 = __expf(m0 - nm0), a1 = __expf(m1 - nm1);
        float sum0 = 0.f, sum1 = 0.f;
#pragma unroll
        for (int nt = 0; nt < 8; nt++) {
            s[nt][0] = __expf(s[nt][0] - nm0);
            s[nt][1] = __expf(s[nt][1] - nm0);
            s[nt][2] = __expf(s[nt][2] - nm1);
            s[nt][3] = __expf(s[nt][3] - nm1);
            sum0 += s[nt][0] + s[nt][1];
            sum1 += s[nt][2] + s[nt][3];
        }
        sum0 += __shfl_xor_sync(0xffffffffu, sum0, 1);
        sum0 += __shfl_xor_sync(0xffffffffu, sum0, 2);
        sum1 += __shfl_xor_sync(0xffffffffu, sum1, 1);
        sum1 += __shfl_xor_sync(0xffffffffu, sum1, 2);

        l0 = l0 * a0 + sum0;
        l1 = l1 * a1 + sum1;
        m0 = nm0; m1 = nm1;
#pragma unroll
        for (int nt = 0; nt < 8; nt++) {
            o[nt][0] *= a0; o[nt][1] *= a0;
            o[nt][2] *= a1; o[nt][3] *= a1;
        }

#pragma unroll
        for (int nt = 0; nt < 8; nt++) {
            *(float2*)&Ps[(warp * 16 + g) * ST + nt * 8 + 2 * tig] =
                make_float2(f2tff(s[nt][0]), f2tff(s[nt][1]));
            *(float2*)&Ps[(warp * 16 + g + 8) * ST + nt * 8 + 2 * tig] =
                make_float2(f2tff(s[nt][2]), f2tff(s[nt][3]));
        }
        __syncwarp();

#pragma unroll
        for (int kc = 0; kc < 8; kc++) {
            unsigned pf[4];
            pf[0] = __float_as_uint(Ps[(warp * 16 + g) * ST + kc * 8 + tig]);
            pf[1] = __float_as_uint(Ps[(warp * 16 + g + 8) * ST + kc * 8 + tig]);
            pf[2] = __float_as_uint(Ps[(warp * 16 + g) * ST + kc * 8 + tig + 4]);
            pf[3] = __float_as_uint(Ps[(warp * 16 + g + 8) * ST + kc * 8 + tig + 4]);
#pragma unroll
            for (int nt = 0; nt < 8; nt++) {
                unsigned b0 = __float_as_uint(Vs[(kc * 8 + tig) * ST + nt * 8 + g]);
                unsigned b1 = __float_as_uint(Vs[(kc * 8 + tig + 4) * ST + nt * 8 + g]);
                mma8(o[nt], pf, b0, b1);
            }
        }
        __syncwarp();
    }

    // epilogue: normalize, round to tf32 (next GEMM input), store
    float inv0 = 1.0f / l0, inv1 = 1.0f / l1;
    float* Cb = Ctx + ((size_t)b * S_LEN + qb + warp * 16) * D_MODEL + h * HEAD_DIM;
#pragma unroll
    for (int nt = 0; nt < 8; nt++) {
        *(float2*)&Cb[(size_t)g * D_MODEL + nt * 8 + 2 * tig] =
            make_float2(f2tff(o[nt][0] * inv0), f2tff(o[nt][1] * inv0));
        *(float2*)&Cb[(size_t)(g + 8) * D_MODEL + nt * 8 + 2 * tig] =
            make_float2(f2tff(o[nt][2] * inv1), f2tff(o[nt][3] * inv1));
    }
}

// =================================================================
// Launch
// =================================================================
extern "C" void kernel_launch(void* const* d_in, const int* in_sizes, int n_in,
                              void* d_out, int out_size)
{
    const float* x  = (const float*)d_in[0];
    const float* Wq = (const float*)d_in[1];
    const float* Wk = (const float*)d_in[2];
    const float* Wv = (const float*)d_in[3];
    const float* Wo = (const float*)d_in[4];
    float* out = (float*)d_out;

    float *Q, *K, *V, *C, *Xr;
    cudaGetSymbolAddress((void**)&Q, g_Q);
    cudaGetSymbolAddress((void**)&K, g_K);
    cudaGetSymbolAddress((void**)&V, g_V);
    cudaGetSymbolAddress((void**)&C, g_C);
    cudaGetSymbolAddress((void**)&Xr, g_Xr);

    // 0: rope table
    rope_table_kernel<<<(S_LEN * 32 + 255) / 256, 256>>>();

    // 1: pre-round x + weights to tf32-valued fp32
    int nr4 = (NTOK * D_MODEL + 4 * D_MODEL * D_MODEL) / 4;
    preround_kernel<<<(nr4 + 255) / 256, 256>>>(x, Wq, Wk, Wv, Wo);

    // 2: fused QKV projections + RoPE epilogue
    qkv_gemm_kernel<<<dim3(D_MODEL / 128, NTOK / 128, 3), 256>>>(Xr);

    // 3: attention
    cudaFuncSetAttribute(attn_tf32, cudaFuncAttributeMaxDynamicSharedMemorySize, ATT_SMEM2);
    attn_tf32<<<dim3(S_LEN / 128, N_HEADS, BATCH), 256, ATT_SMEM2>>>(Q, K, V, C);

    // 4: output projection
    out_gemm_kernel<<<dim3(D_MODEL / 128, NTOK / 128), 256>>>(out);
}